// round 5
// baseline (speedup 1.0000x reference)
#include <cuda_runtime.h>
#include <math.h>

// Problem constants (fixed by reference setup_inputs)
#define BB 4
#define HH 8
#define SS 2048
#define DD 8
#define CAP 32
#define RARE_WARPS 1024   // 128 blocks * 8 warps

// Scratch. g_xn2 is a monotone max over fixed inputs (deterministic across
// replays). g_nrare is reset by k_xmax at the start of every call.
__device__ unsigned g_xn2;
__device__ int      g_nrare;
__device__ int      g_rlist[BB*SS];      // rows with cnt >= 2
__device__ int      g_cnt[BB*SS];
__device__ int      g_cand[BB*SS*CAP];
__device__ float    g_mval[BB*SS*CAP];

// ---------------------------------------------------------------------------
// Kernel 1: max row-norm^2 of x; also resets the rare-row counter.
// ---------------------------------------------------------------------------
__global__ void k_xmax(const float* __restrict__ x) {
    if (blockIdx.x == 0 && threadIdx.x == 0) g_nrare = 0;
    int row = blockIdx.x * blockDim.x + threadIdx.x;   // < 65536
    const float4* xr = (const float4*)(x + (size_t)row * DD);
    float4 a = xr[0], b = xr[1];
    float n = a.x*a.x + a.y*a.y + a.z*a.z + a.w*a.w
            + b.x*b.x + b.y*b.y + b.z*b.z + b.w*b.w;
#pragma unroll
    for (int o = 16; o; o >>= 1)
        n = fmaxf(n, __shfl_xor_sync(0xffffffffu, n, o));
    if ((threadIdx.x & 31) == 0)
        atomicMax(&g_xn2, __float_as_uint(n));   // n >= 0: uint order == float order
}

// ---------------------------------------------------------------------------
// Kernel 2: lean mask-row scan. Block per (b,q) row, 256 threads.
// Streams the 64 MB mask exactly once. Rigorous window: keys with
// mask > min + (2*qb + 30)/1e4 carry < e^-30 relative softmax weight, where
// qb = (|Wq|_F xm + |bq|)(|Wk|_F xm + |bk|)/sqrt(8) bounds every |score|.
// cnt==1 (~99%): weight is exactly 1 -> copy x row for all 8 heads here.
// cnt>=2: push row to compact rare list.
// ---------------------------------------------------------------------------
__global__ void __launch_bounds__(256) k_scan(
        const float* __restrict__ x, const float* __restrict__ mask,
        const float* __restrict__ Wq, const float* __restrict__ bq,
        const float* __restrict__ Wk, const float* __restrict__ bk,
        float* __restrict__ out) {
    int row = blockIdx.x;               // b*SS + q
    int b   = row >> 11;
    int q   = row & (SS - 1);
    int t   = threadIdx.x;

    __shared__ float warpmin[8];
    __shared__ float s_thresh;
    __shared__ int   s_cnt;
    __shared__ int   s_idx[CAP];
    __shared__ float s_mv[CAP];

    const float4* mr = (const float4*)(mask + (size_t)row * SS);
    float4 m0 = mr[t * 2], m1 = mr[t * 2 + 1];

    // thread 0 computes the margin while the rest are stalled on DRAM
    float margin = 0.f;
    if (t == 0) {
        float fq = 0.f, fk = 0.f, nbq = 0.f, nbk = 0.f;
#pragma unroll
        for (int i = 0; i < 64; i++) { float a2 = __ldg(Wq+i), c2 = __ldg(Wk+i); fq += a2*a2; fk += c2*c2; }
#pragma unroll
        for (int i = 0; i < 8;  i++) { float a2 = __ldg(bq+i), c2 = __ldg(bk+i); nbq += a2*a2; nbk += c2*c2; }
        float xm = sqrtf(__uint_as_float(g_xn2));
        float qb = (sqrtf(fq)*xm + sqrtf(nbq)) * (sqrtf(fk)*xm + sqrtf(nbk)) * 0.35355339059f;
        margin = (2.0f * qb + 30.0f) * 1e-4f;
    }

    float v[8] = {m0.x, m0.y, m0.z, m0.w, m1.x, m1.y, m1.z, m1.w};
    float mn = v[0];
#pragma unroll
    for (int j = 1; j < 8; j++) mn = fminf(mn, v[j]);
#pragma unroll
    for (int o = 16; o; o >>= 1) mn = fminf(mn, __shfl_xor_sync(0xffffffffu, mn, o));
    if ((t & 31) == 0) warpmin[t >> 5] = mn;
    __syncthreads();
    if (t == 0) {
        float m = fminf(fminf(fminf(warpmin[0], warpmin[1]), fminf(warpmin[2], warpmin[3])),
                        fminf(fminf(warpmin[4], warpmin[5]), fminf(warpmin[6], warpmin[7])));
        s_thresh = m + margin;
        s_cnt = 0;
    }
    __syncthreads();

    float th = s_thresh;
#pragma unroll
    for (int j = 0; j < 8; j++) {
        if (v[j] <= th) {
            int p = atomicAdd(&s_cnt, 1);
            if (p < CAP) { s_idx[p] = t * 8 + j; s_mv[p] = v[j]; }
        }
    }
    __syncthreads();

    int cnt = s_cnt;
    if (cnt == 1) {
        // exact: single-key softmax == 1 -> copy x row for each head
        if (t < 16) {
            int h = t >> 1, p = t & 1;
            int kk = s_idx[0];
            size_t base = ((size_t)(b * HH + h) * SS);
            const float4* src = (const float4*)(x   + (base + kk) * DD);
            float4*       dst = (float4*)      (out + (base + q ) * DD);
            dst[p] = src[p];
        }
    } else {
        if (t == 0) {
            g_cnt[row] = cnt;
            g_rlist[atomicAdd(&g_nrare, 1)] = row;
        }
        if (t < cnt && t < CAP) {
            g_cand[(size_t)row * CAP + t] = s_idx[t];
            g_mval[(size_t)row * CAP + t] = s_mv[t];
        }
    }
}

// ---------------------------------------------------------------------------
// Kernel 3: compacted rare rows (cnt >= 2). Tiny fixed grid; warp w handles
// task w = (rare index, head). Lane-per-candidate parallel scoring + exact
// warp softmax; warp-strided full-row fallback if the list overflowed.
// ---------------------------------------------------------------------------
__global__ void __launch_bounds__(256) k_rare2(
        const float* __restrict__ x, const float* __restrict__ mask,
        const float* __restrict__ Wq, const float* __restrict__ bq,
        const float* __restrict__ Wk, const float* __restrict__ bk,
        float* __restrict__ out) {
    int gw   = (blockIdx.x * blockDim.x + threadIdx.x) >> 5;
    int lane = threadIdx.x & 31;
    int ntask = g_nrare * HH;

    for (int task = gw; task < ntask; task += RARE_WARPS) {
        int row = g_rlist[task >> 3];
        int h   = task & 7;
        int b   = row >> 11;
        int q   = row & (SS - 1);
        int bh  = b * HH + h;
        const float* xb = x + (size_t)bh * SS * DD;

        // q projection (warp-uniform, cached weight loads)
        const float4* xq = (const float4*)(xb + (size_t)q * DD);
        float4 a0 = xq[0], a1 = xq[1];
        float xv[8] = {a0.x, a0.y, a0.z, a0.w, a1.x, a1.y, a1.z, a1.w};
        float qv[8];
#pragma unroll
        for (int i = 0; i < 8; i++) {
            float s = __ldg(bq + i);
#pragma unroll
            for (int j = 0; j < 8; j++) s += xv[j] * __ldg(Wq + i*8 + j);
            qv[i] = s;
        }

        int cnt = g_cnt[row];
        float acc[8];
        float inv;

        if (cnt <= CAP) {
            // lane i = candidate i; all gathers in flight at once
            float score = -INFINITY;
            float xk[8] = {0,0,0,0,0,0,0,0};
            if (lane < cnt) {
                int kk = g_cand[(size_t)row * CAP + lane];
                const float4* xr = (const float4*)(xb + (size_t)kk * DD);
                float4 c0 = xr[0], c1 = xr[1];
                xk[0]=c0.x; xk[1]=c0.y; xk[2]=c0.z; xk[3]=c0.w;
                xk[4]=c1.x; xk[5]=c1.y; xk[6]=c1.z; xk[7]=c1.w;
                float sdot = 0.f;
#pragma unroll
                for (int i = 0; i < 8; i++) {
                    float kv = __ldg(bk + i);
#pragma unroll
                    for (int j = 0; j < 8; j++) kv += xk[j] * __ldg(Wk + i*8 + j);
                    sdot += qv[i] * kv;
                }
                score = sdot * 0.35355339059f - 10000.0f * g_mval[(size_t)row * CAP + lane];
            }
            float m = score;
#pragma unroll
            for (int o = 16; o; o >>= 1) m = fmaxf(m, __shfl_xor_sync(0xffffffffu, m, o));
            float p = (lane < cnt) ? expf(score - m) : 0.f;
            float l = p;
#pragma unroll
            for (int o = 16; o; o >>= 1) l += __shfl_xor_sync(0xffffffffu, l, o);
#pragma unroll
            for (int i = 0; i < 8; i++) {
                float s = p * xk[i];
#pragma unroll
                for (int o = 16; o; o >>= 1) s += __shfl_xor_sync(0xffffffffu, s, o);
                acc[i] = s;
            }
            inv = 1.0f / l;
        } else {
            // exact full-row fallback: lanes stride keys, online softmax
            const float* mrow = mask + (size_t)row * SS;
            float m = -INFINITY, l = 0.f;
#pragma unroll
            for (int i = 0; i < 8; i++) acc[i] = 0.f;
            for (int kk = lane; kk < SS; kk += 32) {
                const float4* xr = (const float4*)(xb + (size_t)kk * DD);
                float4 c0 = xr[0], c1 = xr[1];
                float xk[8] = {c0.x,c0.y,c0.z,c0.w,c1.x,c1.y,c1.z,c1.w};
                float sdot = 0.f;
#pragma unroll
                for (int i = 0; i < 8; i++) {
                    float kv = __ldg(bk + i);
#pragma unroll
                    for (int j = 0; j < 8; j++) kv += xk[j] * __ldg(Wk + i*8 + j);
                    sdot += qv[i] * kv;
                }
                float sc = sdot * 0.35355339059f - 10000.0f * mrow[kk];
                float nm = fmaxf(m, sc);
                float corr = expf(m - nm);
                float p = expf(sc - nm);
                l = l * corr + p;
#pragma unroll
                for (int i = 0; i < 8; i++) acc[i] = acc[i]*corr + p*xk[i];
                m = nm;
            }
#pragma unroll
            for (int o = 16; o; o >>= 1) {
                float om = __shfl_xor_sync(0xffffffffu, m, o);
                float ol = __shfl_xor_sync(0xffffffffu, l, o);
                float oa[8];
#pragma unroll
                for (int i = 0; i < 8; i++) oa[i] = __shfl_xor_sync(0xffffffffu, acc[i], o);
                float nm = fmaxf(m, om);
                float c1 = expf(m - nm), c2 = expf(om - nm);
                l = l * c1 + ol * c2;
#pragma unroll
                for (int i = 0; i < 8; i++) acc[i] = acc[i]*c1 + oa[i]*c2;
                m = nm;
            }
            inv = 1.0f / l;
        }

        if (lane == 0) {
            float4* o = (float4*)(out + ((size_t)bh * SS + q) * DD);
            o[0] = make_float4(acc[0]*inv, acc[1]*inv, acc[2]*inv, acc[3]*inv);
            o[1] = make_float4(acc[4]*inv, acc[5]*inv, acc[6]*inv, acc[7]*inv);
        }
    }
}

extern "C" void kernel_launch(void* const* d_in, const int* in_sizes, int n_in,
                              void* d_out, int out_size) {
    const float* x    = (const float*)d_in[0];  // [4,8,2048,8]
    const float* mask = (const float*)d_in[1];  // [4,1,2048,2048]
    const float* Wq   = (const float*)d_in[2];  // [8,8]
    const float* bq   = (const float*)d_in[3];  // [8]
    const float* Wk   = (const float*)d_in[4];  // [8,8]
    const float* bk   = (const float*)d_in[5];  // [8]
    float* out = (float*)d_out;                 // [4,8,2048,8]

    k_xmax<<<(BB*HH*SS)/256, 256>>>(x);
    k_scan<<<BB*SS, 256>>>(x, mask, Wq, bq, Wk, bk, out);
    k_rare2<<<RARE_WARPS/8, 256>>>(x, mask, Wq, bq, Wk, bk, out);
}

// round 6
// speedup vs baseline: 1.0955x; 1.0955x over previous
#include <cuda_runtime.h>
#include <math.h>

// Problem constants (fixed by reference setup_inputs)
#define BB 4
#define HH 8
#define SS 2048
#define DD 8
#define CAP 32
#define XBLOCKS 64
#define XTHREADS 256
#define RARE_BLOCKS 64   // 512 warps

// Scratch. g_xn2 is a monotone max over fixed inputs (deterministic across
// replays). g_done returns to 0 at the end of each k_xmax (last block resets).
__device__ unsigned g_xn2;
__device__ int      g_done;
__device__ float    g_margin;
__device__ int      g_nrare;
__device__ int      g_rlist[BB*SS];      // rows with cnt >= 2
__device__ int      g_cnt[BB*SS];
__device__ int      g_cand[BB*SS*CAP];
__device__ float    g_mval[BB*SS*CAP];

// ---------------------------------------------------------------------------
// Kernel 1: max row-norm^2 of x (4 rows/thread, 8 loads in flight), then the
// last block to finish derives the rigorous candidate margin:
//   |score| <= qb = (|Wq|_F xm + |bq|)(|Wk|_F xm + |bk|)/sqrt(8)
//   keys with mask > min + (2*qb + 30)/1e4 carry < e^-30 relative weight.
// Also resets the rare-row counter for this call.
// ---------------------------------------------------------------------------
__global__ void __launch_bounds__(XTHREADS) k_xmax(
        const float* __restrict__ x,
        const float* __restrict__ Wq, const float* __restrict__ bq,
        const float* __restrict__ Wk, const float* __restrict__ bk) {
    if (blockIdx.x == 0 && threadIdx.x == 0) g_nrare = 0;

    int tg = blockIdx.x * XTHREADS + threadIdx.x;    // < 16384
    float n = 0.f;
#pragma unroll
    for (int i = 0; i < 4; i++) {
        int row = tg + i * (XBLOCKS * XTHREADS);     // coalesced row chunks
        const float4* xr = (const float4*)(x + (size_t)row * DD);
        float4 a = xr[0], b = xr[1];
        float r = a.x*a.x + a.y*a.y + a.z*a.z + a.w*a.w
                + b.x*b.x + b.y*b.y + b.z*b.z + b.w*b.w;
        n = fmaxf(n, r);
    }
#pragma unroll
    for (int o = 16; o; o >>= 1)
        n = fmaxf(n, __shfl_xor_sync(0xffffffffu, n, o));

    __shared__ float wmax[XTHREADS/32];
    if ((threadIdx.x & 31) == 0) wmax[threadIdx.x >> 5] = n;
    __syncthreads();
    if (threadIdx.x == 0) {
        float m = wmax[0];
#pragma unroll
        for (int i = 1; i < XTHREADS/32; i++) m = fmaxf(m, wmax[i]);
        atomicMax(&g_xn2, __float_as_uint(m));   // m >= 0: uint order == float order
        __threadfence();
        int old = atomicAdd(&g_done, 1);
        if (old == XBLOCKS - 1) {                // last block: g_xn2 is final
            float fq = 0.f, fk = 0.f, nbq = 0.f, nbk = 0.f;
            for (int i = 0; i < 64; i++) { float a = Wq[i], c = Wk[i]; fq += a*a; fk += c*c; }
            for (int i = 0; i < 8;  i++) { float a = bq[i], c = bk[i]; nbq += a*a; nbk += c*c; }
            float xm = sqrtf(__uint_as_float(g_xn2));
            float qb = (sqrtf(fq)*xm + sqrtf(nbq)) * (sqrtf(fk)*xm + sqrtf(nbk)) * 0.35355339059f;
            g_margin = (2.0f * qb + 30.0f) * 1e-4f;
            g_done = 0;                          // reset for next replay
        }
    }
}

// ---------------------------------------------------------------------------
// Kernel 2: lean mask-row scan. Block per (b,q) row, 256 threads.
// Streams the 64 MB mask exactly once. cnt==1 (~99%): softmax weight is
// exactly 1 -> copy x row for all 8 heads here. cnt>=2: push to rare list.
// ---------------------------------------------------------------------------
__global__ void __launch_bounds__(256) k_scan(
        const float* __restrict__ x, const float* __restrict__ mask,
        float* __restrict__ out) {
    int row = blockIdx.x;               // b*SS + q
    int b   = row >> 11;
    int q   = row & (SS - 1);
    int t   = threadIdx.x;

    __shared__ float warpmin[8];
    __shared__ float s_thresh;
    __shared__ int   s_cnt;
    __shared__ int   s_idx[CAP];
    __shared__ float s_mv[CAP];

    const float4* mr = (const float4*)(mask + (size_t)row * SS);
    float4 m0 = mr[t * 2], m1 = mr[t * 2 + 1];
    float v[8] = {m0.x, m0.y, m0.z, m0.w, m1.x, m1.y, m1.z, m1.w};

    float mn = v[0];
#pragma unroll
    for (int j = 1; j < 8; j++) mn = fminf(mn, v[j]);
#pragma unroll
    for (int o = 16; o; o >>= 1) mn = fminf(mn, __shfl_xor_sync(0xffffffffu, mn, o));
    if ((t & 31) == 0) warpmin[t >> 5] = mn;
    __syncthreads();
    if (t == 0) {
        float m = fminf(fminf(fminf(warpmin[0], warpmin[1]), fminf(warpmin[2], warpmin[3])),
                        fminf(fminf(warpmin[4], warpmin[5]), fminf(warpmin[6], warpmin[7])));
        s_thresh = m + g_margin;
        s_cnt = 0;
    }
    __syncthreads();

    float th = s_thresh;
#pragma unroll
    for (int j = 0; j < 8; j++) {
        if (v[j] <= th) {
            int p = atomicAdd(&s_cnt, 1);
            if (p < CAP) { s_idx[p] = t * 8 + j; s_mv[p] = v[j]; }
        }
    }
    __syncthreads();

    int cnt = s_cnt;
    if (cnt == 1) {
        // exact: single-key softmax == 1 -> copy x row for each head
        if (t < 16) {
            int h = t >> 1, p = t & 1;
            int kk = s_idx[0];
            size_t base = ((size_t)(b * HH + h) * SS);
            const float4* src = (const float4*)(x   + (base + kk) * DD);
            float4*       dst = (float4*)      (out + (base + q ) * DD);
            dst[p] = src[p];
        }
    } else {
        if (t == 0) {
            g_cnt[row] = cnt;
            g_rlist[atomicAdd(&g_nrare, 1)] = row;
        }
        if (t < cnt && t < CAP) {
            g_cand[(size_t)row * CAP + t] = s_idx[t];
            g_mval[(size_t)row * CAP + t] = s_mv[t];
        }
    }
}

// ---------------------------------------------------------------------------
// Kernel 3: compacted rare rows (cnt >= 2). Warp per (rare row, head) task.
// Lane-per-candidate parallel scoring + exact warp softmax; warp-strided
// full-row fallback if the candidate list overflowed.
// ---------------------------------------------------------------------------
__global__ void __launch_bounds__(256) k_rare2(
        const float* __restrict__ x, const float* __restrict__ mask,
        const float* __restrict__ Wq, const float* __restrict__ bq,
        const float* __restrict__ Wk, const float* __restrict__ bk,
        float* __restrict__ out) {
    int gw   = (blockIdx.x * blockDim.x + threadIdx.x) >> 5;
    int lane = threadIdx.x & 31;
    int ntask = g_nrare * HH;

    for (int task = gw; task < ntask; task += RARE_BLOCKS * 8) {
        int row = g_rlist[task >> 3];
        int h   = task & 7;
        int b   = row >> 11;
        int q   = row & (SS - 1);
        int bh  = b * HH + h;
        const float* xb = x + (size_t)bh * SS * DD;

        const float4* xq = (const float4*)(xb + (size_t)q * DD);
        float4 a0 = xq[0], a1 = xq[1];
        float xv[8] = {a0.x, a0.y, a0.z, a0.w, a1.x, a1.y, a1.z, a1.w};
        float qv[8];
#pragma unroll
        for (int i = 0; i < 8; i++) {
            float s = __ldg(bq + i);
#pragma unroll
            for (int j = 0; j < 8; j++) s += xv[j] * __ldg(Wq + i*8 + j);
            qv[i] = s;
        }

        int cnt = g_cnt[row];
        float acc[8];
        float inv;

        if (cnt <= CAP) {
            float score = -INFINITY;
            float xk[8] = {0,0,0,0,0,0,0,0};
            if (lane < cnt) {
                int kk = g_cand[(size_t)row * CAP + lane];
                const float4* xr = (const float4*)(xb + (size_t)kk * DD);
                float4 c0 = xr[0], c1 = xr[1];
                xk[0]=c0.x; xk[1]=c0.y; xk[2]=c0.z; xk[3]=c0.w;
                xk[4]=c1.x; xk[5]=c1.y; xk[6]=c1.z; xk[7]=c1.w;
                float sdot = 0.f;
#pragma unroll
                for (int i = 0; i < 8; i++) {
                    float kv = __ldg(bk + i);
#pragma unroll
                    for (int j = 0; j < 8; j++) kv += xk[j] * __ldg(Wk + i*8 + j);
                    sdot += qv[i] * kv;
                }
                score = sdot * 0.35355339059f - 10000.0f * g_mval[(size_t)row * CAP + lane];
            }
            float m = score;
#pragma unroll
            for (int o = 16; o; o >>= 1) m = fmaxf(m, __shfl_xor_sync(0xffffffffu, m, o));
            float p = (lane < cnt) ? expf(score - m) : 0.f;
            float l = p;
#pragma unroll
            for (int o = 16; o; o >>= 1) l += __shfl_xor_sync(0xffffffffu, l, o);
#pragma unroll
            for (int i = 0; i < 8; i++) {
                float s = p * xk[i];
#pragma unroll
                for (int o = 16; o; o >>= 1) s += __shfl_xor_sync(0xffffffffu, s, o);
                acc[i] = s;
            }
            inv = 1.0f / l;
        } else {
            const float* mrow = mask + (size_t)row * SS;
            float m = -INFINITY, l = 0.f;
#pragma unroll
            for (int i = 0; i < 8; i++) acc[i] = 0.f;
            for (int kk = lane; kk < SS; kk += 32) {
                const float4* xr = (const float4*)(xb + (size_t)kk * DD);
                float4 c0 = xr[0], c1 = xr[1];
                float xk[8] = {c0.x,c0.y,c0.z,c0.w,c1.x,c1.y,c1.z,c1.w};
                float sdot = 0.f;
#pragma unroll
                for (int i = 0; i < 8; i++) {
                    float kv = __ldg(bk + i);
#pragma unroll
                    for (int j = 0; j < 8; j++) kv += xk[j] * __ldg(Wk + i*8 + j);
                    sdot += qv[i] * kv;
                }
                float sc = sdot * 0.35355339059f - 10000.0f * mrow[kk];
                float nm = fmaxf(m, sc);
                float corr = expf(m - nm);
                float p = expf(sc - nm);
                l = l * corr + p;
#pragma unroll
                for (int i = 0; i < 8; i++) acc[i] = acc[i]*corr + p*xk[i];
                m = nm;
            }
#pragma unroll
            for (int o = 16; o; o >>= 1) {
                float om = __shfl_xor_sync(0xffffffffu, m, o);
                float ol = __shfl_xor_sync(0xffffffffu, l, o);
                float oa[8];
#pragma unroll
                for (int i = 0; i < 8; i++) oa[i] = __shfl_xor_sync(0xffffffffu, acc[i], o);
                float nm = fmaxf(m, om);
                float c1 = expf(m - nm), c2 = expf(om - nm);
                l = l * c1 + ol * c2;
#pragma unroll
                for (int i = 0; i < 8; i++) acc[i] = acc[i]*c1 + oa[i]*c2;
                m = nm;
            }
            inv = 1.0f / l;
        }

        if (lane == 0) {
            float4* o = (float4*)(out + ((size_t)bh * SS + q) * DD);
            o[0] = make_float4(acc[0]*inv, acc[1]*inv, acc[2]*inv, acc[3]*inv);
            o[1] = make_float4(acc[4]*inv, acc[5]*inv, acc[6]*inv, acc[7]*inv);
        }
    }
}

extern "C" void kernel_launch(void* const* d_in, const int* in_sizes, int n_in,
                              void* d_out, int out_size) {
    const float* x    = (const float*)d_in[0];  // [4,8,2048,8]
    const float* mask = (const float*)d_in[1];  // [4,1,2048,2048]
    const float* Wq   = (const float*)d_in[2];  // [8,8]
    const float* bq   = (const float*)d_in[3];  // [8]
    const float* Wk   = (const float*)d_in[4];  // [8,8]
    const float* bk   = (const float*)d_in[5];  // [8]
    float* out = (float*)d_out;                 // [4,8,2048,8]

    k_xmax<<<XBLOCKS, XTHREADS>>>(x, Wq, bq, Wk, bk);
    k_scan<<<BB*SS, 256>>>(x, mask, out);
    k_rare2<<<RARE_BLOCKS, 256>>>(x, mask, Wq, bq, Wk, bk, out);
}

// round 7
// speedup vs baseline: 1.1468x; 1.0468x over previous
#include <cuda_runtime.h>
#include <math.h>

// Problem constants (fixed by reference setup_inputs)
#define BB 4
#define HH 8
#define SS 2048
#define DD 8
#define CAP 32
#define RARE_BLOCKS 128           // 1024 warps
#define M0 0.02f                  // speculative margin; verified in k_rare2

// Scratch. g_xn2 is a monotone max over fixed inputs (same value every call).
// g_nrare is reset by the last k_rare2 block each call; g_done2 likewise.
__device__ unsigned g_xn2;
__device__ int      g_nrare;
__device__ int      g_done2;
__device__ int      g_rlist[BB*SS];      // rows with cnt >= 2
__device__ int      g_cnt[BB*SS];
__device__ int      g_cand[BB*SS*CAP];
__device__ float    g_mval[BB*SS*CAP];

// ---------------------------------------------------------------------------
// Kernel 1: lean mask-row scan. Block per (b,q) row, 256 threads.
// Streams the 64 MB mask exactly once, with a tiny x-norm side-task
// (8 x-rows per block -> global atomicMax into g_xn2, complete by kernel end).
// Candidate window uses the fixed speculative margin M0. cnt==1 (~96%):
// softmax weight is exactly 1 -> copy x row for all 8 heads here.
// cnt>=2: push row to the compact rare list.
// ---------------------------------------------------------------------------
__global__ void __launch_bounds__(256) k_scan(
        const float* __restrict__ x, const float* __restrict__ mask,
        float* __restrict__ out) {
    int row = blockIdx.x;               // b*SS + q
    int b   = row >> 11;
    int q   = row & (SS - 1);
    int t   = threadIdx.x;

    __shared__ float warpmin[8];
    __shared__ float s_thresh;
    __shared__ int   s_cnt;
    __shared__ int   s_idx[CAP];
    __shared__ float s_mv[CAP];

    const float4* mr = (const float4*)(mask + (size_t)row * SS);
    float4 m0 = mr[t * 2], m1 = mr[t * 2 + 1];

    // side-task: x-norm partials (rows 8*blockIdx .. +8), 16 threads, 4 floats each
    float xn = 0.f;
    if (t < 16) {
        int xrow = blockIdx.x * 8 + (t >> 1);
        const float4* xr = (const float4*)(x + (size_t)xrow * DD) + (t & 1);
        float4 a = *xr;
        xn = a.x*a.x + a.y*a.y + a.z*a.z + a.w*a.w;
    }

    float v[8] = {m0.x, m0.y, m0.z, m0.w, m1.x, m1.y, m1.z, m1.w};
    float mn = v[0];
#pragma unroll
    for (int j = 1; j < 8; j++) mn = fminf(mn, v[j]);
#pragma unroll
    for (int o = 16; o; o >>= 1) mn = fminf(mn, __shfl_xor_sync(0xffffffffu, mn, o));
    if ((t & 31) == 0) warpmin[t >> 5] = mn;

    if (t < 32) {    // warp 0 finishes the x-norm reduction
#pragma unroll
        for (int o = 8; o; o >>= 1) xn = fmaxf(xn, __shfl_xor_sync(0xffffffffu, xn, o));
        if (t == 0) atomicMax(&g_xn2, __float_as_uint(xn));   // xn>=0: uint==float order
    }
    __syncthreads();
    if (t == 0) {
        float m = fminf(fminf(fminf(warpmin[0], warpmin[1]), fminf(warpmin[2], warpmin[3])),
                        fminf(fminf(warpmin[4], warpmin[5]), fminf(warpmin[6], warpmin[7])));
        s_thresh = m + M0;
        s_cnt = 0;
    }
    __syncthreads();

    float th = s_thresh;
#pragma unroll
    for (int j = 0; j < 8; j++) {
        if (v[j] <= th) {
            int p = atomicAdd(&s_cnt, 1);
            if (p < CAP) { s_idx[p] = t * 8 + j; s_mv[p] = v[j]; }
        }
    }
    __syncthreads();

    int cnt = s_cnt;
    if (cnt == 1) {
        // exact: single-key softmax == 1 -> copy x row for each head
        if (t < 16) {
            int h = t >> 1, p = t & 1;
            int kk = s_idx[0];
            size_t base = ((size_t)(b * HH + h) * SS);
            const float4* src = (const float4*)(x   + (base + kk) * DD);
            float4*       dst = (float4*)      (out + (base + q ) * DD);
            dst[p] = src[p];
        }
    } else {
        if (t == 0) {
            g_cnt[row] = cnt;
            g_rlist[atomicAdd(&g_nrare, 1)] = row;
        }
        if (t < cnt && t < CAP) {
            g_cand[(size_t)row * CAP + t] = s_idx[t];
            g_mval[(size_t)row * CAP + t] = s_mv[t];
        }
    }
}

// ---------------------------------------------------------------------------
// Kernel 2: rare rows + rigor verification.
// First verifies the speculative margin: M* = (2*qb + 30)*1e-4 with
// qb = (|Wq|_F xm + |bq|)(|Wk|_F xm + |bk|)/sqrt(8), xm = sqrt(g_xn2).
// If M* <= M0 (always, for this data), only cnt>=2 rows need exact work:
// warp per (rare row, head), lane-per-candidate scoring + exact warp softmax,
// warp-strided full-row fallback if a candidate list overflowed.
// If M* > M0, recompute EVERY row exactly (never taken; correctness net).
// Last block resets g_nrare for the next graph replay.
// ---------------------------------------------------------------------------
__global__ void __launch_bounds__(256) k_rare2(
        const float* __restrict__ x, const float* __restrict__ mask,
        const float* __restrict__ Wq, const float* __restrict__ bq,
        const float* __restrict__ Wk, const float* __restrict__ bk,
        float* __restrict__ out) {
    __shared__ float s_red[64];
    __shared__ int   s_fb;

    int t = threadIdx.x;
    // parallel weight reduction: threads 0..63 handle Wq/Wk element i
    float wq2 = 0.f, wk2 = 0.f, bq2 = 0.f, bk2 = 0.f;
    if (t < 64) { float a = Wq[t], c = Wk[t]; wq2 = a*a; wk2 = c*c; }
    if (t < 8)  { float a = bq[t], c = bk[t]; bq2 = a*a; bk2 = c*c; }
    // pack: reduce within first two warps via shared
    if (t < 64) s_red[t] = wq2 + bq2 * 1.0f;   // placeholder; do exact sums below
    __syncthreads();
    if (t == 0) {
        float fq = 0.f, fk = 0.f, nbq = 0.f, nbk = 0.f;
        // values already in L1/L2 from the parallel touch above
        for (int i = 0; i < 64; i++) { float a = Wq[i], c = Wk[i]; fq += a*a; fk += c*c; }
        for (int i = 0; i < 8;  i++) { float a = bq[i], c = bk[i]; nbq += a*a; nbk += c*c; }
        float xm = sqrtf(__uint_as_float(g_xn2));
        float qb = (sqrtf(fq)*xm + sqrtf(nbq)) * (sqrtf(fk)*xm + sqrtf(nbk)) * 0.35355339059f;
        float mstar = (2.0f * qb + 30.0f) * 1e-4f;
        s_fb = (mstar > M0) ? 1 : 0;
    }
    __syncthreads();

    int  fb    = s_fb;
    int  gw    = (blockIdx.x * blockDim.x + t) >> 5;
    int  lane  = t & 31;
    int  ntask = fb ? (BB * SS * HH) : (g_nrare * HH);
    int  nw    = RARE_BLOCKS * 8;

    for (int task = gw; task < ntask; task += nw) {
        int row = fb ? (task >> 3) : g_rlist[task >> 3];
        int h   = task & 7;
        int b   = row >> 11;
        int q   = row & (SS - 1);
        int bh  = b * HH + h;
        const float* xb = x + (size_t)bh * SS * DD;

        const float4* xq = (const float4*)(xb + (size_t)q * DD);
        float4 a0 = xq[0], a1 = xq[1];
        float xv[8] = {a0.x, a0.y, a0.z, a0.w, a1.x, a1.y, a1.z, a1.w};
        float qv[8];
#pragma unroll
        for (int i = 0; i < 8; i++) {
            float s = __ldg(bq + i);
#pragma unroll
            for (int j = 0; j < 8; j++) s += xv[j] * __ldg(Wq + i*8 + j);
            qv[i] = s;
        }

        int cnt = fb ? (SS + 1) : g_cnt[row];
        float acc[8];
        float inv;

        if (cnt <= CAP) {
            float score = -INFINITY;
            float xk[8] = {0,0,0,0,0,0,0,0};
            if (lane < cnt) {
                int kk = g_cand[(size_t)row * CAP + lane];
                const float4* xr = (const float4*)(xb + (size_t)kk * DD);
                float4 c0 = xr[0], c1 = xr[1];
                xk[0]=c0.x; xk[1]=c0.y; xk[2]=c0.z; xk[3]=c0.w;
                xk[4]=c1.x; xk[5]=c1.y; xk[6]=c1.z; xk[7]=c1.w;
                float sdot = 0.f;
#pragma unroll
                for (int i = 0; i < 8; i++) {
                    float kv = __ldg(bk + i);
#pragma unroll
                    for (int j = 0; j < 8; j++) kv += xk[j] * __ldg(Wk + i*8 + j);
                    sdot += qv[i] * kv;
                }
                score = sdot * 0.35355339059f - 10000.0f * g_mval[(size_t)row * CAP + lane];
            }
            float m = score;
#pragma unroll
            for (int o = 16; o; o >>= 1) m = fmaxf(m, __shfl_xor_sync(0xffffffffu, m, o));
            float p = (lane < cnt) ? expf(score - m) : 0.f;
            float l = p;
#pragma unroll
            for (int o = 16; o; o >>= 1) l += __shfl_xor_sync(0xffffffffu, l, o);
#pragma unroll
            for (int i = 0; i < 8; i++) {
                float s = p * xk[i];
#pragma unroll
                for (int o = 16; o; o >>= 1) s += __shfl_xor_sync(0xffffffffu, s, o);
                acc[i] = s;
            }
            inv = 1.0f / l;
        } else {
            const float* mrow = mask + (size_t)(b * SS + q) * SS;
            float m = -INFINITY, l = 0.f;
#pragma unroll
            for (int i = 0; i < 8; i++) acc[i] = 0.f;
            for (int kk = lane; kk < SS; kk += 32) {
                const float4* xr = (const float4*)(xb + (size_t)kk * DD);
                float4 c0 = xr[0], c1 = xr[1];
                float xk[8] = {c0.x,c0.y,c0.z,c0.w,c1.x,c1.y,c1.z,c1.w};
                float sdot = 0.f;
#pragma unroll
                for (int i = 0; i < 8; i++) {
                    float kv = __ldg(bk + i);
#pragma unroll
                    for (int j = 0; j < 8; j++) kv += xk[j] * __ldg(Wk + i*8 + j);
                    sdot += qv[i] * kv;
                }
                float sc = sdot * 0.35355339059f - 10000.0f * mrow[kk];
                float nm = fmaxf(m, sc);
                float corr = expf(m - nm);
                float p = expf(sc - nm);
                l = l * corr + p;
#pragma unroll
                for (int i = 0; i < 8; i++) acc[i] = acc[i]*corr + p*xk[i];
                m = nm;
            }
#pragma unroll
            for (int o = 16; o; o >>= 1) {
                float om = __shfl_xor_sync(0xffffffffu, m, o);
                float ol = __shfl_xor_sync(0xffffffffu, l, o);
                float oa[8];
#pragma unroll
                for (int i = 0; i < 8; i++) oa[i] = __shfl_xor_sync(0xffffffffu, acc[i], o);
                float nm = fmaxf(m, om);
                float c1 = expf(m - nm), c2 = expf(om - nm);
                l = l * c1 + ol * c2;
#pragma unroll
                for (int i = 0; i < 8; i++) acc[i] = acc[i]*c1 + oa[i]*c2;
                m = nm;
            }
            inv = 1.0f / l;
        }

        if (lane == 0) {
            float4* o = (float4*)(out + ((size_t)bh * SS + q) * DD);
            o[0] = make_float4(acc[0]*inv, acc[1]*inv, acc[2]*inv, acc[3]*inv);
            o[1] = make_float4(acc[4]*inv, acc[5]*inv, acc[6]*inv, acc[7]*inv);
        }
    }

    // last block resets per-call state for the next graph replay
    __syncthreads();
    if (t == 0) {
        __threadfence();
        int old = atomicAdd(&g_done2, 1);
        if (old == RARE_BLOCKS - 1) { g_nrare = 0; g_done2 = 0; }
    }
}

extern "C" void kernel_launch(void* const* d_in, const int* in_sizes, int n_in,
                              void* d_out, int out_size) {
    const float* x    = (const float*)d_in[0];  // [4,8,2048,8]
    const float* mask = (const float*)d_in[1];  // [4,1,2048,2048]
    const float* Wq   = (const float*)d_in[2];  // [8,8]
    const float* bq   = (const float*)d_in[3];  // [8]
    const float* Wk   = (const float*)d_in[4];  // [8,8]
    const float* bk   = (const float*)d_in[5];  // [8]
    float* out = (float*)d_out;                 // [4,8,2048,8]

    k_scan<<<BB*SS, 256>>>(x, mask, out);
    k_rare2<<<RARE_BLOCKS, 256>>>(x, mask, Wq, bq, Wk, bk, out);
}

// round 8
// speedup vs baseline: 1.4993x; 1.3074x over previous
#include <cuda_runtime.h>
#include <math.h>

// Problem constants (fixed by reference setup_inputs)
#define BB 4
#define HH 8
#define SS 2048
#define DD 8
#define CAP 32
#define RARE_BLOCKS 32            // 8192 threads, thread-per-task
#define M0 0.015f                 // speculative margin; verified in k_rare3

// Scratch. g_xn2 is a monotone max over fixed inputs (same value every call).
// g_nrare is reset by the last k_rare3 block each call; g_done2 likewise.
__device__ unsigned g_xn2;
__device__ int      g_nrare;
__device__ int      g_done2;
__device__ int      g_rlist[BB*SS];      // rows with cnt >= 2
__device__ int      g_cnt[BB*SS];
__device__ int      g_cand[BB*SS*CAP];
__device__ float    g_mval[BB*SS*CAP];

// ---------------------------------------------------------------------------
// Kernel 1: lean mask-row scan. Block per (b,q) row, 256 threads.
// Streams the 64 MB mask exactly once, with a tiny x-norm side-task
// (8 x-rows per block -> global atomicMax into g_xn2, complete by kernel end).
// Candidate window uses the fixed speculative margin M0 (verified later).
// cnt==1 (~96%): softmax weight is exactly 1 -> copy x row for all 8 heads.
// cnt>=2: push row to the compact rare list.
// ---------------------------------------------------------------------------
__global__ void __launch_bounds__(256) k_scan(
        const float* __restrict__ x, const float* __restrict__ mask,
        float* __restrict__ out) {
    int row = blockIdx.x;               // b*SS + q
    int b   = row >> 11;
    int q   = row & (SS - 1);
    int t   = threadIdx.x;

    __shared__ float warpmin[8];
    __shared__ float s_thresh;
    __shared__ int   s_cnt;
    __shared__ int   s_idx[CAP];
    __shared__ float s_mv[CAP];

    const float4* mr = (const float4*)(mask + (size_t)row * SS);
    float4 m0 = mr[t * 2], m1 = mr[t * 2 + 1];

    // side-task: x-norm partials (rows 8*blockIdx .. +8), 16 threads, 4 floats each
    float xn = 0.f;
    if (t < 16) {
        int xrow = blockIdx.x * 8 + (t >> 1);
        const float4* xr = (const float4*)(x + (size_t)xrow * DD) + (t & 1);
        float4 a = *xr;
        xn = a.x*a.x + a.y*a.y + a.z*a.z + a.w*a.w;
    }

    float v[8] = {m0.x, m0.y, m0.z, m0.w, m1.x, m1.y, m1.z, m1.w};
    float mn = v[0];
#pragma unroll
    for (int j = 1; j < 8; j++) mn = fminf(mn, v[j]);
#pragma unroll
    for (int o = 16; o; o >>= 1) mn = fminf(mn, __shfl_xor_sync(0xffffffffu, mn, o));
    if ((t & 31) == 0) warpmin[t >> 5] = mn;

    if (t < 32) {    // warp 0 finishes the x-norm side reduction
#pragma unroll
        for (int o = 8; o; o >>= 1) xn = fmaxf(xn, __shfl_xor_sync(0xffffffffu, xn, o));
        if (t == 0) atomicMax(&g_xn2, __float_as_uint(xn));   // xn>=0: uint==float order
    }
    __syncthreads();
    if (t == 0) {
        float m = fminf(fminf(fminf(warpmin[0], warpmin[1]), fminf(warpmin[2], warpmin[3])),
                        fminf(fminf(warpmin[4], warpmin[5]), fminf(warpmin[6], warpmin[7])));
        s_thresh = m + M0;
        s_cnt = 0;
    }
    __syncthreads();

    float th = s_thresh;
#pragma unroll
    for (int j = 0; j < 8; j++) {
        if (v[j] <= th) {
            int p = atomicAdd(&s_cnt, 1);
            if (p < CAP) { s_idx[p] = t * 8 + j; s_mv[p] = v[j]; }
        }
    }
    __syncthreads();

    int cnt = s_cnt;
    if (cnt == 1) {
        if (t < 16) {
            int h = t >> 1, p = t & 1;
            int kk = s_idx[0];
            size_t base = ((size_t)(b * HH + h) * SS);
            const float4* src = (const float4*)(x   + (base + kk) * DD);
            float4*       dst = (float4*)      (out + (base + q ) * DD);
            dst[p] = src[p];
        }
    } else {
        if (t == 0) {
            g_cnt[row] = cnt;
            g_rlist[atomicAdd(&g_nrare, 1)] = row;
        }
        if (t < cnt && t < CAP) {
            g_cand[(size_t)row * CAP + t] = s_idx[t];
            g_mval[(size_t)row * CAP + t] = s_mv[t];
        }
    }
}

// ---------------------------------------------------------------------------
// Kernel 2: rare rows, thread-per-(row,head) task + rigor verification.
// Verifies M* = (2*qb + 30)*1e-4 <= M0 with
// qb = (|Wq|_F xm + |bq|)(|Wk|_F xm + |bk|)/sqrt(8), xm = sqrt(g_xn2);
// every key outside the window then carries < e^-30 relative softmax weight.
// If verification failed (never, for this data), recomputes EVERY row exactly.
// ~2900 independent tasks over 8192 threads: one wave, latency overlapped,
// no inter-thread reductions. Candidate lists are tiny (cnt ~ 2-3); overflow
// (cnt > CAP) falls back to an exact full-row loop. Last block resets g_nrare.
// ---------------------------------------------------------------------------
__global__ void __launch_bounds__(256) k_rare3(
        const float* __restrict__ x, const float* __restrict__ mask,
        const float* __restrict__ Wq, const float* __restrict__ bq,
        const float* __restrict__ Wk, const float* __restrict__ bk,
        float* __restrict__ out) {
    __shared__ float sWq[64], sWk[64], sbq[8], sbk[8];
    __shared__ int   s_fb;

    int t = threadIdx.x;
    if (t < 64)       { sWq[t] = Wq[t]; sWk[t] = Wk[t]; }
    else if (t < 72)  sbq[t - 64] = bq[t - 64];
    else if (t < 80)  sbk[t - 72] = bk[t - 72];
    __syncthreads();

    if (t == 0) {
        float fq = 0.f, fk = 0.f, nbq = 0.f, nbk = 0.f;
#pragma unroll
        for (int i = 0; i < 64; i++) { fq += sWq[i]*sWq[i]; fk += sWk[i]*sWk[i]; }
#pragma unroll
        for (int i = 0; i < 8;  i++) { nbq += sbq[i]*sbq[i]; nbk += sbk[i]*sbk[i]; }
        float xm = sqrtf(__uint_as_float(g_xn2));
        float qb = (sqrtf(fq)*xm + sqrtf(nbq)) * (sqrtf(fk)*xm + sqrtf(nbk)) * 0.35355339059f;
        float mstar = (2.0f * qb + 30.0f) * 1e-4f;
        s_fb = (mstar > M0) ? 1 : 0;
    }
    __syncthreads();

    int fb     = s_fb;
    int ntask  = (fb ? (BB * SS) : g_nrare) * HH;
    int stride = RARE_BLOCKS * 256;

    for (int task = blockIdx.x * 256 + t; task < ntask; task += stride) {
        int row = fb ? (task >> 3) : g_rlist[task >> 3];
        int h   = task & 7;
        int b   = row >> 11;
        int q   = row & (SS - 1);
        int bh  = b * HH + h;
        const float* xb = x + (size_t)bh * SS * DD;

        // q projection from shared weights
        const float4* xq = (const float4*)(xb + (size_t)q * DD);
        float4 a0 = xq[0], a1 = xq[1];
        float xv[8] = {a0.x, a0.y, a0.z, a0.w, a1.x, a1.y, a1.z, a1.w};
        float qv[8];
#pragma unroll
        for (int i = 0; i < 8; i++) {
            float s = sbq[i];
#pragma unroll
            for (int j = 0; j < 8; j++) s += xv[j] * sWq[i*8 + j];
            qv[i] = s;
        }

        int cnt = fb ? (SS + 1) : g_cnt[row];
        bool full = (cnt > CAP);
        int n = full ? SS : cnt;
        const int*   cl   = g_cand + (size_t)row * CAP;
        const float* mv   = g_mval + (size_t)row * CAP;
        const float* mrow = mask + (size_t)(b * SS + q) * SS;

        float m = -INFINITY, l = 0.f;
        float acc[8] = {0,0,0,0,0,0,0,0};

        for (int i = 0; i < n; i++) {
            int   kk = full ? i : cl[i];
            float mm = full ? mrow[kk] : mv[i];
            const float4* xr = (const float4*)(xb + (size_t)kk * DD);
            float4 c0 = xr[0], c1 = xr[1];
            float xk[8] = {c0.x,c0.y,c0.z,c0.w,c1.x,c1.y,c1.z,c1.w};
            float sdot = 0.f;
#pragma unroll
            for (int i2 = 0; i2 < 8; i2++) {
                float kv = sbk[i2];
#pragma unroll
                for (int j = 0; j < 8; j++) kv += xk[j] * sWk[i2*8 + j];
                sdot += qv[i2] * kv;
            }
            float sc = sdot * 0.35355339059f - 10000.0f * mm;
            float nm = fmaxf(m, sc);
            float corr = expf(m - nm);
            float p = expf(sc - nm);
            l = l * corr + p;
#pragma unroll
            for (int i2 = 0; i2 < 8; i2++) acc[i2] = acc[i2]*corr + p*xk[i2];
            m = nm;
        }

        float inv = 1.0f / l;
        float4* o = (float4*)(out + ((size_t)bh * SS + q) * DD);
        o[0] = make_float4(acc[0]*inv, acc[1]*inv, acc[2]*inv, acc[3]*inv);
        o[1] = make_float4(acc[4]*inv, acc[5]*inv, acc[6]*inv, acc[7]*inv);
    }

    // last block resets per-call state for the next graph replay
    __syncthreads();
    if (t == 0) {
        __threadfence();
        int old = atomicAdd(&g_done2, 1);
        if (old == RARE_BLOCKS - 1) { g_nrare = 0; g_done2 = 0; }
    }
}

extern "C" void kernel_launch(void* const* d_in, const int* in_sizes, int n_in,
                              void* d_out, int out_size) {
    const float* x    = (const float*)d_in[0];  // [4,8,2048,8]
    const float* mask = (const float*)d_in[1];  // [4,1,2048,2048]
    const float* Wq   = (const float*)d_in[2];  // [8,8]
    const float* bq   = (const float*)d_in[3];  // [8]
    const float* Wk   = (const float*)d_in[4];  // [8,8]
    const float* bk   = (const float*)d_in[5];  // [8]
    float* out = (float*)d_out;                 // [4,8,2048,8]

    k_scan<<<BB*SS, 256>>>(x, mask, out);
    k_rare3<<<RARE_BLOCKS, 256>>>(x, mask, Wq, bq, Wk, bk, out);
}